// round 12
// baseline (speedup 1.0000x reference)
#include <cuda_runtime.h>
#include <cuda_fp16.h>
#include <math.h>
#include <stdint.h>

#define B 4
#define P 2048
#define C 512
#define D 1024
#define H 16
#define DH 64

// ---------------- scratch (static device arrays) ----------------
__device__ __half g_q[(size_t)B * H * P * DH];
__device__ __half g_k[(size_t)B * H * C * DH];
__device__ __half g_v[(size_t)B * H * C * DH];
__device__ float g_ctx[(size_t)B * P * D];
__device__ __half g_pa[(size_t)B * P * D];
__device__ __half g_cl[(size_t)B * C * D];
__device__ __half g_wt[(size_t)3 * D * D];
__device__ __half g_ed[(size_t)B * P * C];

__device__ __forceinline__ uint32_t smem_u32(const void* p) {
    uint32_t a;
    asm("{ .reg .u64 t; cvta.to.shared.u64 t, %1; cvt.u32.u64 %0, t; }"
        : "=r"(a) : "l"(p));
    return a;
}

// ---------------- mma.sync helpers (fp16 in, fp32 accum) ----------------
__device__ __forceinline__ void ldsm_x4(uint32_t& r0, uint32_t& r1,
                                        uint32_t& r2, uint32_t& r3, uint32_t a) {
    asm volatile("ldmatrix.sync.aligned.m8n8.x4.shared.b16 {%0,%1,%2,%3}, [%4];"
                 : "=r"(r0), "=r"(r1), "=r"(r2), "=r"(r3) : "r"(a));
}
__device__ __forceinline__ void ldsm_x2t(uint32_t& r0, uint32_t& r1, uint32_t a) {
    asm volatile("ldmatrix.sync.aligned.m8n8.x2.trans.shared.b16 {%0,%1}, [%2];"
                 : "=r"(r0), "=r"(r1) : "r"(a));
}
__device__ __forceinline__ void mma16816(float* d, const uint32_t* a,
                                         const uint32_t* b) {
    asm volatile(
        "mma.sync.aligned.m16n8k16.row.col.f32.f16.f16.f32 "
        "{%0,%1,%2,%3}, {%4,%5,%6,%7}, {%8,%9}, {%0,%1,%2,%3};"
        : "+f"(d[0]), "+f"(d[1]), "+f"(d[2]), "+f"(d[3])
        : "r"(a[0]), "r"(a[1]), "r"(a[2]), "r"(a[3]), "r"(b[0]), "r"(b[1]));
}
__device__ __forceinline__ void cp16(uint32_t dst, const void* src) {
    asm volatile("cp.async.cg.shared.global [%0], [%1], 16;"
                 :: "r"(dst), "l"(src));
}
#define CP_COMMIT() asm volatile("cp.async.commit_group;" ::: "memory")
#define CP_WAIT0()  asm volatile("cp.async.wait_group 0;" ::: "memory")
#define CP_WAIT1()  asm volatile("cp.async.wait_group 1;" ::: "memory")

// pack two f32 -> f16x2 (first arg in LOW half)
__device__ __forceinline__ uint32_t pkhf(float lo, float hi) {
    uint32_t d;
    asm("cvt.rn.f16x2.f32 %0, %1, %2;" : "=r"(d) : "f"(hi), "f"(lo));
    return d;
}
__device__ __forceinline__ float exp2r(float x) {
    float y; asm("ex2.approx.ftz.f32 %0, %1;" : "=f"(y) : "f"(x)); return y;
}

// =====================================================================
// Merged prep: para/cluster/edge fp16 convert | W transpose fp16.
// =====================================================================
#define PA_BLKS ((B * P * D) / 1024)        // 8192
#define CL_BLKS ((B * C * D) / 1024)        // 2048
#define ED_BLKS ((B * P * C) / 1024)        // 4096
#define WT_BLKS (32 * 32 * 3)               // 3072
#define PREP_BLKS (PA_BLKS + CL_BLKS + ED_BLKS + WT_BLKS)

__global__ void __launch_bounds__(256) prep_all(
    const float* __restrict__ para, const float* __restrict__ cluster,
    const float* __restrict__ edge,
    const float* __restrict__ Wq, const float* __restrict__ Wk,
    const float* __restrict__ Wv,
    __half* __restrict__ pa, __half* __restrict__ cl,
    __half* __restrict__ ed, __half* __restrict__ wt)
{
    const int bid = blockIdx.x;
    if (bid < PA_BLKS + CL_BLKS + ED_BLKS) {
        const float* x;
        __half* o;
        size_t base;
        if (bid < PA_BLKS) { x = para; o = pa; base = (size_t)bid * 1024; }
        else if (bid < PA_BLKS + CL_BLKS) {
            x = cluster; o = cl; base = (size_t)(bid - PA_BLKS) * 1024;
        } else {
            x = edge; o = ed; base = (size_t)(bid - PA_BLKS - CL_BLKS) * 1024;
        }
        size_t i = base + (size_t)threadIdx.x * 4;
        float4 v = *(const float4*)(x + i);
        __half2 p0{__float2half_rn(v.x), __float2half_rn(v.y)};
        __half2 p1{__float2half_rn(v.z), __float2half_rn(v.w)};
        *(__half2*)(o + i) = p0;
        *(__half2*)(o + i + 2) = p1;
        return;
    }
    __shared__ float t[32][33];
    const int wb = bid - PA_BLKS - CL_BLKS - ED_BLKS;
    const int wz = wb >> 10;
    const int rem = wb & 1023;
    const int kb = (rem & 31) * 32, nb = (rem >> 5) * 32;
    const float* W = (wz == 0) ? Wq : (wz == 1) ? Wk : Wv;
    size_t ooff = (size_t)wz * D * D;
    int tx = threadIdx.x & 31, ty = threadIdx.x >> 5;
#pragma unroll
    for (int j = 0; j < 4; j++)
        t[ty + j * 8][tx] = W[(size_t)(kb + ty + j * 8) * D + nb + tx];
    __syncthreads();
#pragma unroll
    for (int j = 0; j < 4; j++) {
        int n = nb + ty + j * 8, kk = kb + tx;
        wt[ooff + (size_t)n * D + kk] = __float2half_rn(t[tx][ty + j * 8]);
    }
}

// =====================================================================
// Projection GEMM: pure fp16 single-pass, 3-stage cp.async ring,
// warp grid 4(m) x 2(n), K chunks of 64.
// =====================================================================
#define PST 144
#define ARR_B (128 * PST)                  // 18432
#define STAGE_B (2 * ARR_B)                // 36864
#define PROJ_SMEM_BYTES (3 * STAGE_B)      // 110592

__global__ void __launch_bounds__(256, 2) proj_mma(
    const __half* __restrict__ pa, const __half* __restrict__ cl,
    const __half* __restrict__ wt,
    const float* __restrict__ bq, const float* __restrict__ bk,
    const float* __restrict__ bv,
    __half* __restrict__ q, __half* __restrict__ k, __half* __restrict__ v)
{
    extern __shared__ char smem[];
    const uint32_t sbase = smem_u32(smem);
    const int tid = threadIdx.x;
    const int wid = tid >> 5, lane = tid & 31;

    const int bid = blockIdx.x;
    const __half *X, *W;
    const float* bias;
    __half* o;
    int mblk, Lsh; float scale;
    if (bid < 512) {
        X = pa; W = wt;
        bias = bq; o = q; Lsh = 11;
        scale = 0.125f * 1.44269504f;
        mblk = bid >> 3;
    } else if (bid < 640) {
        X = cl; W = wt + (size_t)D * D;
        bias = bk; o = k; Lsh = 9; scale = 1.0f;
        mblk = (bid - 512) >> 3;
    } else {
        X = cl; W = wt + (size_t)2 * D * D;
        bias = bv; o = v; Lsh = 9; scale = 1.0f;
        mblk = (bid - 640) >> 3;
    }
    const int n0 = (bid & 7) * 128;
    const int m0 = mblk * 128;

    const int wm = wid >> 1, wn = wid & 1;

    auto stage_load = [&](int stg, int k0) {
        const uint32_t sb = sbase + (uint32_t)stg * STAGE_B;
        const __half* srcs[2] = {X, W};
        const int rowoff[2] = {m0, n0};
#pragma unroll
        for (int a = 0; a < 2; a++) {
            const __half* s = srcs[a];
            uint32_t ab = sb + a * ARR_B;
#pragma unroll
            for (int i = 0; i < 4; i++) {
                int idx = tid + i * 256;
                int row = idx >> 3, seg = idx & 7;
                cp16(ab + row * PST + seg * 16,
                     s + (size_t)(rowoff[a] + row) * D + k0 + seg * 8);
            }
        }
    };

    float acc[2][8][4];
#pragma unroll
    for (int i = 0; i < 2; i++)
#pragma unroll
        for (int j = 0; j < 8; j++)
#pragma unroll
            for (int qq = 0; qq < 4; qq++) acc[i][j][qq] = 0.f;

    const int a_row_in = (lane & 7) + 8 * ((lane >> 3) & 1);
    const int a_colb = (lane >> 4) * 16;
    const int b4_row = ((lane >> 4) & 1) * 8 + (lane & 7);
    const int b4_colb = ((lane >> 3) & 1) * 16;

    stage_load(0, 0);
    CP_COMMIT();
    stage_load(1, 64);
    CP_COMMIT();
    CP_WAIT1();
    __syncthreads();

    for (int ck = 0; ck < 16; ck++) {
        if (ck + 2 < 16) stage_load((ck + 2) % 3, (ck + 2) * 64);
        CP_COMMIT();

        const uint32_t sb = sbase + (uint32_t)(ck % 3) * STAGE_B;
        const uint32_t xs = sb, ws = sb + ARR_B;

#pragma unroll
        for (int ks = 0; ks < 4; ks++) {
            const int kb = ks * 32;
            uint32_t bf[8][2];
#pragma unroll
            for (int pi = 0; pi < 4; pi++) {
                uint32_t boff =
                    (uint32_t)(wn * 64 + pi * 16 + b4_row) * PST + kb + b4_colb;
                ldsm_x4(bf[2 * pi][0], bf[2 * pi][1],
                        bf[2 * pi + 1][0], bf[2 * pi + 1][1], ws + boff);
            }
#pragma unroll
            for (int mi = 0; mi < 2; mi++) {
                uint32_t aoff =
                    (uint32_t)(wm * 32 + mi * 16 + a_row_in) * PST + kb + a_colb;
                uint32_t af[4];
                ldsm_x4(af[0], af[1], af[2], af[3], xs + aoff);
#pragma unroll
                for (int ni = 0; ni < 8; ni++) mma16816(acc[mi][ni], af, bf[ni]);
            }
        }
        CP_WAIT1();
        __syncthreads();
    }

    // epilogue
    const int qr = lane >> 2;
    const int qc = (lane & 3) * 2;
    const int L = 1 << Lsh, Lm = L - 1;
#pragma unroll
    for (int mi = 0; mi < 2; mi++) {
#pragma unroll
        for (int rh = 0; rh < 2; rh++) {
            int m = m0 + wm * 32 + mi * 16 + qr + rh * 8;
            int bb = m >> Lsh, l = m & Lm;
#pragma unroll
            for (int ni = 0; ni < 8; ni++) {
                int n = n0 + wn * 64 + ni * 8 + qc;
                int hh = n >> 6, d0 = n & 63;
                float ox = (acc[mi][ni][rh * 2 + 0] + bias[n]) * scale;
                float oy = (acc[mi][ni][rh * 2 + 1] + bias[n + 1]) * scale;
                size_t off = (((size_t)bb * H + hh) * (size_t)L + l) * DH + d0;
                *(uint32_t*)(o + off) = pkhf(ox, oy);
            }
        }
    }
}

// =====================================================================
// Fused attention: pure fp16, fp16 edge, 3-stage cp.async ring,
// CT=32, exp2 softmax.
// Stage layout: K 0 (32x144), V 4608 (32x144), E 9216 (128 rows x 80B).
// =====================================================================
#define AST 144
#define EST 80
#define STG0 18432
#define STG_SZ 19456
#define ATTN_SMEM_BYTES (STG0 + 3 * STG_SZ)

__global__ void __launch_bounds__(256, 2) attn_mma(
    const __half* __restrict__ q, const __half* __restrict__ k,
    const __half* __restrict__ v,
    const __half* __restrict__ ed, float* __restrict__ ctx)
{
    extern __shared__ char smem[];
    const uint32_t sbase = smem_u32(smem);
    const int tid = threadIdx.x;
    const int wid = tid >> 5, lane = tid & 31;
    const int b = blockIdx.z, h = blockIdx.y;
    const int p0 = blockIdx.x * 128;

    const size_t qoff = (((size_t)b * H + h) * P + p0) * DH;
    const size_t koff = (((size_t)b * H + h) * C) * DH;
    const __half* ebase = ed + ((size_t)b * P + p0) * C;

    const int krow = tid >> 3, kseg = tid & 7;
    const int erow = tid >> 2, eseg = tid & 3;

    auto load_chunk = [&](uint32_t stg, int cn) {
        cp16(stg + krow * AST + kseg * 16,
             k + koff + (size_t)(cn + krow) * DH + kseg * 8);
        cp16(stg + 4608 + krow * AST + kseg * 16,
             v + koff + (size_t)(cn + krow) * DH + kseg * 8);
#pragma unroll
        for (int i = 0; i < 2; i++) {
            int er = erow + i * 64;
            cp16(stg + 9216 + er * EST + eseg * 16,
                 ebase + (size_t)er * C + cn + eseg * 8);
        }
    };

    // prologue: Q + chunk0 (group 0), chunk1 (group 1)
#pragma unroll
    for (int i = 0; i < 4; i++) {
        int g = tid + i * 256;
        int row = g >> 3, seg = g & 7;
        cp16(sbase + row * AST + seg * 16,
             q + qoff + (size_t)row * DH + seg * 8);
    }
    load_chunk(sbase + STG0, 0);
    CP_COMMIT();
    load_chunk(sbase + STG0 + STG_SZ, 32);
    CP_COMMIT();

    const int a_row = (lane & 7) + 8 * ((lane >> 3) & 1);
    const int a_colb = (lane >> 4) * 16;
    const int b4_row = ((lane >> 4) & 1) * 8 + (lane & 7);
    const int b4_colb = ((lane >> 3) & 1) * 16;
    const int r0 = lane >> 2;
    const int wr = wid * 16;
    const int c2 = (lane & 3) * 2;

    CP_WAIT1();
    __syncthreads();

    uint32_t qf[4][4];
#pragma unroll
    for (int ks = 0; ks < 4; ks++) {
        uint32_t aoff = (uint32_t)(wr + a_row) * AST + a_colb + ks * 32;
        ldsm_x4(qf[ks][0], qf[ks][1], qf[ks][2], qf[ks][3], sbase + aoff);
    }

    float m_r[2] = {-1e30f, -1e30f};
    float l_r[2] = {0.f, 0.f};
    float cacc[8][4];
#pragma unroll
    for (int i = 0; i < 8; i++)
#pragma unroll
        for (int j = 0; j < 4; j++) cacc[i][j] = 0.f;

    for (int ck = 0; ck < 16; ck++) {
        if (ck + 2 < 16)
            load_chunk(sbase + STG0 + (uint32_t)((ck + 2) % 3) * STG_SZ,
                       (ck + 2) * 32);
        CP_COMMIT();

        const uint32_t stgoff = STG0 + (uint32_t)(ck % 3) * STG_SZ;
        const uint32_t stg = sbase + stgoff;

        // ---- S = Q K^T ----
        float s[4][4];
#pragma unroll
        for (int i = 0; i < 4; i++)
#pragma unroll
            for (int j = 0; j < 4; j++) s[i][j] = 0.f;

#pragma unroll
        for (int ks = 0; ks < 4; ks++) {
            uint32_t bf[4][2];
#pragma unroll
            for (int pi = 0; pi < 2; pi++) {
                uint32_t boff =
                    (uint32_t)(pi * 16 + b4_row) * AST + b4_colb + ks * 32;
                ldsm_x4(bf[2 * pi][0], bf[2 * pi][1],
                        bf[2 * pi + 1][0], bf[2 * pi + 1][1], stg + boff);
            }
#pragma unroll
            for (int ni = 0; ni < 4; ni++) mma16816(s[ni], qf[ks], bf[ni]);
        }

        // ---- online softmax (exp2 domain, fp16 edge) ----
        float alpha[2];
#pragma unroll
        for (int rr = 0; rr < 2; rr++) {
            const __half* ep = (const __half*)(smem + stgoff + 9216 +
                                (size_t)(wr + r0 + rr * 8) * EST) + c2;
            float ev[4][2];
            float mx = -1e30f;
#pragma unroll
            for (int j = 0; j < 4; j++) {
                float2 e2 = __half22float2(*(const __half2*)(ep + j * 8));
                ev[j][0] = e2.x; ev[j][1] = e2.y;
                float s0 = (e2.x > 0.f) ? s[j][rr * 2] : -1e30f;
                float s1 = (e2.y > 0.f) ? s[j][rr * 2 + 1] : -1e30f;
                s[j][rr * 2] = s0; s[j][rr * 2 + 1] = s1;
                mx = fmaxf(mx, fmaxf(s0, s1));
            }
            mx = fmaxf(mx, __shfl_xor_sync(0xffffffffu, mx, 1));
            mx = fmaxf(mx, __shfl_xor_sync(0xffffffffu, mx, 2));
            float mn = fmaxf(m_r[rr], mx);
            alpha[rr] = exp2r(m_r[rr] - mn);
            m_r[rr] = mn;
            float ls = 0.f;
#pragma unroll
            for (int j = 0; j < 4; j++) {
                float ex0 = exp2r(s[j][rr * 2] - mn);
                float ex1 = exp2r(s[j][rr * 2 + 1] - mn);
                ls += ex0 + ex1;
                s[j][rr * 2] = ex0 * ev[j][0];
                s[j][rr * 2 + 1] = ex1 * ev[j][1];
            }
            ls += __shfl_xor_sync(0xffffffffu, ls, 1);
            ls += __shfl_xor_sync(0xffffffffu, ls, 2);
            l_r[rr] = l_r[rr] * alpha[rr] + ls;
        }

        // ---- rescale ctx, then ctx += P V ----
#pragma unroll
        for (int ni = 0; ni < 8; ni++) {
            cacc[ni][0] *= alpha[0]; cacc[ni][1] *= alpha[0];
            cacc[ni][2] *= alpha[1]; cacc[ni][3] *= alpha[1];
        }
#pragma unroll
        for (int ks = 0; ks < 2; ks++) {
            const float* t0 = s[2 * ks];
            const float* t1 = s[2 * ks + 1];
            uint32_t ap[4];
            ap[0] = pkhf(t0[0], t0[1]);
            ap[1] = pkhf(t0[2], t0[3]);
            ap[2] = pkhf(t1[0], t1[1]);
            ap[3] = pkhf(t1[2], t1[3]);
            uint32_t vrow = (uint32_t)(ks * 16 + (lane & 15)) * AST;
            uint32_t vf[8][2];
#pragma unroll
            for (int ni = 0; ni < 8; ni++)
                ldsm_x2t(vf[ni][0], vf[ni][1], stg + 4608 + vrow + ni * 16);
#pragma unroll
            for (int ni = 0; ni < 8; ni++) mma16816(cacc[ni], ap, vf[ni]);
        }

        CP_WAIT1();
        __syncthreads();
    }

    const float inv0 = 1.0f / l_r[0];
    const float inv1 = 1.0f / l_r[1];
    const int row0 = p0 + wr + r0;
#pragma unroll
    for (int ni = 0; ni < 8; ni++) {
        int dh = ni * 8 + c2;
        size_t base0 = ((size_t)b * P + row0) * D + h * DH + dh;
        float2 o0{cacc[ni][0] * inv0, cacc[ni][1] * inv0};
        float2 o1{cacc[ni][2] * inv1, cacc[ni][3] * inv1};
        *(float2*)(ctx + base0) = o0;
        *(float2*)(ctx + base0 + (size_t)8 * D) = o1;
    }
}

// =====================================================================
// LayerNorm over D=1024.
// =====================================================================
__global__ void __launch_bounds__(256) ln_kernel(
    const float* __restrict__ x, const float* __restrict__ gamma,
    const float* __restrict__ beta, float* __restrict__ out)
{
    __shared__ float rs1[8], rs2[8];
    const int row = blockIdx.x;
    const int tid = threadIdx.x;
    const float4 xv = *(const float4*)(x + (size_t)row * D + tid * 4);
    float s1 = xv.x + xv.y + xv.z + xv.w;
    float s2 = xv.x * xv.x + xv.y * xv.y + xv.z * xv.z + xv.w * xv.w;
#pragma unroll
    for (int o = 16; o; o >>= 1) {
        s1 += __shfl_xor_sync(0xffffffffu, s1, o);
        s2 += __shfl_xor_sync(0xffffffffu, s2, o);
    }
    if ((tid & 31) == 0) { rs1[tid >> 5] = s1; rs2[tid >> 5] = s2; }
    __syncthreads();
    if (tid < 32) {
        float t1 = (tid < 8) ? rs1[tid] : 0.f;
        float t2 = (tid < 8) ? rs2[tid] : 0.f;
#pragma unroll
        for (int o = 4; o; o >>= 1) {
            t1 += __shfl_xor_sync(0xffffffffu, t1, o);
            t2 += __shfl_xor_sync(0xffffffffu, t2, o);
        }
        if (tid == 0) { rs1[0] = t1; rs2[0] = t2; }
    }
    __syncthreads();
    const float mu = rs1[0] * (1.0f / D);
    const float var = fmaxf(rs2[0] * (1.0f / D) - mu * mu, 0.f);
    const float r = rsqrtf(var + 1e-6f);
    const float4 g = *(const float4*)(gamma + tid * 4);
    const float4 bt = *(const float4*)(beta + tid * 4);
    float4 o;
    o.x = (xv.x - mu) * r * g.x + bt.x;
    o.y = (xv.y - mu) * r * g.y + bt.y;
    o.z = (xv.z - mu) * r * g.z + bt.z;
    o.w = (xv.w - mu) * r * g.w + bt.w;
    *(float4*)(out + (size_t)row * D + tid * 4) = o;
}

// =====================================================================
extern "C" void kernel_launch(void* const* d_in, const int* in_sizes, int n_in,
                              void* d_out, int out_size)
{
    const float* para    = (const float*)d_in[0];
    const float* cluster = (const float*)d_in[1];
    const float* edge    = (const float*)d_in[2];
    const float* Wq = (const float*)d_in[3];
    const float* bq = (const float*)d_in[4];
    const float* Wk = (const float*)d_in[5];
    const float* bk = (const float*)d_in[6];
    const float* Wv = (const float*)d_in[7];
    const float* bv = (const float*)d_in[8];
    const float* gamma = (const float*)d_in[9];
    const float* beta  = (const float*)d_in[10];
    float* out = (float*)d_out;

    float* cp;
    __half *qp, *kp, *vp, *pap, *clp, *wtp, *edp;
    cudaGetSymbolAddress((void**)&cp, g_ctx);
    cudaGetSymbolAddress((void**)&qp, g_q);
    cudaGetSymbolAddress((void**)&kp, g_k);
    cudaGetSymbolAddress((void**)&vp, g_v);
    cudaGetSymbolAddress((void**)&pap, g_pa);
    cudaGetSymbolAddress((void**)&clp, g_cl);
    cudaGetSymbolAddress((void**)&wtp, g_wt);
    cudaGetSymbolAddress((void**)&edp, g_ed);

    cudaFuncSetAttribute(proj_mma,
                         cudaFuncAttributeMaxDynamicSharedMemorySize,
                         PROJ_SMEM_BYTES);
    cudaFuncSetAttribute(attn_mma,
                         cudaFuncAttributeMaxDynamicSharedMemorySize,
                         ATTN_SMEM_BYTES);

    prep_all<<<PREP_BLKS, 256>>>(para, cluster, edge, Wq, Wk, Wv,
                                 pap, clp, edp, wtp);

    proj_mma<<<768, 256, PROJ_SMEM_BYTES>>>(pap, clp, wtp, bq, bk, bv,
                                            qp, kp, vp);

    attn_mma<<<dim3(P / 128, H, B), 256, ATTN_SMEM_BYTES>>>(
        qp, kp, vp, edp, cp);

    ln_kernel<<<B * P, 256>>>(cp, gamma, beta, out);
}

// round 13
// speedup vs baseline: 1.0138x; 1.0138x over previous
#include <cuda_runtime.h>
#include <cuda_fp16.h>
#include <math.h>
#include <stdint.h>

#define B 4
#define P 2048
#define C 512
#define D 1024
#define H 16
#define DH 64

// ---------------- scratch (static device arrays) ----------------
__device__ __half g_q[(size_t)B * H * P * DH];
__device__ __half g_k[(size_t)B * H * C * DH];
__device__ __half g_v[(size_t)B * H * C * DH];
__device__ float g_ctx[(size_t)B * P * D];
__device__ __half g_pa[(size_t)B * P * D];
__device__ __half g_cl[(size_t)B * C * D];
__device__ __half g_wt[(size_t)3 * D * D];
__device__ __half g_ed[(size_t)B * P * C];

__device__ __forceinline__ uint32_t smem_u32(const void* p) {
    uint32_t a;
    asm("{ .reg .u64 t; cvta.to.shared.u64 t, %1; cvt.u32.u64 %0, t; }"
        : "=r"(a) : "l"(p));
    return a;
}

// ---------------- mma.sync helpers (fp16 in, fp32 accum) ----------------
__device__ __forceinline__ void ldsm_x4(uint32_t& r0, uint32_t& r1,
                                        uint32_t& r2, uint32_t& r3, uint32_t a) {
    asm volatile("ldmatrix.sync.aligned.m8n8.x4.shared.b16 {%0,%1,%2,%3}, [%4];"
                 : "=r"(r0), "=r"(r1), "=r"(r2), "=r"(r3) : "r"(a));
}
__device__ __forceinline__ void ldsm_x2t(uint32_t& r0, uint32_t& r1, uint32_t a) {
    asm volatile("ldmatrix.sync.aligned.m8n8.x2.trans.shared.b16 {%0,%1}, [%2];"
                 : "=r"(r0), "=r"(r1) : "r"(a));
}
__device__ __forceinline__ void mma16816(float* d, const uint32_t* a,
                                         const uint32_t* b) {
    asm volatile(
        "mma.sync.aligned.m16n8k16.row.col.f32.f16.f16.f32 "
        "{%0,%1,%2,%3}, {%4,%5,%6,%7}, {%8,%9}, {%0,%1,%2,%3};"
        : "+f"(d[0]), "+f"(d[1]), "+f"(d[2]), "+f"(d[3])
        : "r"(a[0]), "r"(a[1]), "r"(a[2]), "r"(a[3]), "r"(b[0]), "r"(b[1]));
}
__device__ __forceinline__ void cp16(uint32_t dst, const void* src) {
    asm volatile("cp.async.cg.shared.global [%0], [%1], 16;"
                 :: "r"(dst), "l"(src));
}
#define CP_COMMIT() asm volatile("cp.async.commit_group;" ::: "memory")
#define CP_WAIT0()  asm volatile("cp.async.wait_group 0;" ::: "memory")
#define CP_WAIT1()  asm volatile("cp.async.wait_group 1;" ::: "memory")

// pack two f32 -> f16x2 (first arg in LOW half)
__device__ __forceinline__ uint32_t pkhf(float lo, float hi) {
    uint32_t d;
    asm("cvt.rn.f16x2.f32 %0, %1, %2;" : "=r"(d) : "f"(hi), "f"(lo));
    return d;
}
__device__ __forceinline__ float exp2r(float x) {
    float y; asm("ex2.approx.ftz.f32 %0, %1;" : "=f"(y) : "f"(x)); return y;
}

// =====================================================================
// Merged prep: para/cluster/edge fp16 convert | W transpose fp16.
// =====================================================================
#define PA_BLKS ((B * P * D) / 1024)        // 8192
#define CL_BLKS ((B * C * D) / 1024)        // 2048
#define ED_BLKS ((B * P * C) / 1024)        // 4096
#define WT_BLKS (32 * 32 * 3)               // 3072
#define PREP_BLKS (PA_BLKS + CL_BLKS + ED_BLKS + WT_BLKS)

__global__ void __launch_bounds__(256) prep_all(
    const float* __restrict__ para, const float* __restrict__ cluster,
    const float* __restrict__ edge,
    const float* __restrict__ Wq, const float* __restrict__ Wk,
    const float* __restrict__ Wv,
    __half* __restrict__ pa, __half* __restrict__ cl,
    __half* __restrict__ ed, __half* __restrict__ wt)
{
    const int bid = blockIdx.x;
    if (bid < PA_BLKS + CL_BLKS + ED_BLKS) {
        const float* x;
        __half* o;
        size_t base;
        if (bid < PA_BLKS) { x = para; o = pa; base = (size_t)bid * 1024; }
        else if (bid < PA_BLKS + CL_BLKS) {
            x = cluster; o = cl; base = (size_t)(bid - PA_BLKS) * 1024;
        } else {
            x = edge; o = ed; base = (size_t)(bid - PA_BLKS - CL_BLKS) * 1024;
        }
        size_t i = base + (size_t)threadIdx.x * 4;
        float4 v = *(const float4*)(x + i);
        __half2 p0{__float2half_rn(v.x), __float2half_rn(v.y)};
        __half2 p1{__float2half_rn(v.z), __float2half_rn(v.w)};
        *(__half2*)(o + i) = p0;
        *(__half2*)(o + i + 2) = p1;
        return;
    }
    __shared__ float t[32][33];
    const int wb = bid - PA_BLKS - CL_BLKS - ED_BLKS;
    const int wz = wb >> 10;
    const int rem = wb & 1023;
    const int kb = (rem & 31) * 32, nb = (rem >> 5) * 32;
    const float* W = (wz == 0) ? Wq : (wz == 1) ? Wk : Wv;
    size_t ooff = (size_t)wz * D * D;
    int tx = threadIdx.x & 31, ty = threadIdx.x >> 5;
#pragma unroll
    for (int j = 0; j < 4; j++)
        t[ty + j * 8][tx] = W[(size_t)(kb + ty + j * 8) * D + nb + tx];
    __syncthreads();
#pragma unroll
    for (int j = 0; j < 4; j++) {
        int n = nb + ty + j * 8, kk = kb + tx;
        wt[ooff + (size_t)n * D + kk] = __float2half_rn(t[tx][ty + j * 8]);
    }
}

// =====================================================================
// Projection GEMM: pure fp16 single-pass, 3-stage cp.async ring,
// warp grid 4(m) x 2(n), K chunks of 64.  (unchanged from R12)
// =====================================================================
#define PST 144
#define ARR_B (128 * PST)
#define STAGE_B (2 * ARR_B)
#define PROJ_SMEM_BYTES (3 * STAGE_B)

__global__ void __launch_bounds__(256, 2) proj_mma(
    const __half* __restrict__ pa, const __half* __restrict__ cl,
    const __half* __restrict__ wt,
    const float* __restrict__ bq, const float* __restrict__ bk,
    const float* __restrict__ bv,
    __half* __restrict__ q, __half* __restrict__ k, __half* __restrict__ v)
{
    extern __shared__ char smem[];
    const uint32_t sbase = smem_u32(smem);
    const int tid = threadIdx.x;
    const int wid = tid >> 5, lane = tid & 31;

    const int bid = blockIdx.x;
    const __half *X, *W;
    const float* bias;
    __half* o;
    int mblk, Lsh; float scale;
    if (bid < 512) {
        X = pa; W = wt;
        bias = bq; o = q; Lsh = 11;
        scale = 0.125f * 1.44269504f;
        mblk = bid >> 3;
    } else if (bid < 640) {
        X = cl; W = wt + (size_t)D * D;
        bias = bk; o = k; Lsh = 9; scale = 1.0f;
        mblk = (bid - 512) >> 3;
    } else {
        X = cl; W = wt + (size_t)2 * D * D;
        bias = bv; o = v; Lsh = 9; scale = 1.0f;
        mblk = (bid - 640) >> 3;
    }
    const int n0 = (bid & 7) * 128;
    const int m0 = mblk * 128;

    const int wm = wid >> 1, wn = wid & 1;

    auto stage_load = [&](int stg, int k0) {
        const uint32_t sb = sbase + (uint32_t)stg * STAGE_B;
        const __half* srcs[2] = {X, W};
        const int rowoff[2] = {m0, n0};
#pragma unroll
        for (int a = 0; a < 2; a++) {
            const __half* s = srcs[a];
            uint32_t ab = sb + a * ARR_B;
#pragma unroll
            for (int i = 0; i < 4; i++) {
                int idx = tid + i * 256;
                int row = idx >> 3, seg = idx & 7;
                cp16(ab + row * PST + seg * 16,
                     s + (size_t)(rowoff[a] + row) * D + k0 + seg * 8);
            }
        }
    };

    float acc[2][8][4];
#pragma unroll
    for (int i = 0; i < 2; i++)
#pragma unroll
        for (int j = 0; j < 8; j++)
#pragma unroll
            for (int qq = 0; qq < 4; qq++) acc[i][j][qq] = 0.f;

    const int a_row_in = (lane & 7) + 8 * ((lane >> 3) & 1);
    const int a_colb = (lane >> 4) * 16;
    const int b4_row = ((lane >> 4) & 1) * 8 + (lane & 7);
    const int b4_colb = ((lane >> 3) & 1) * 16;

    stage_load(0, 0);
    CP_COMMIT();
    stage_load(1, 64);
    CP_COMMIT();
    CP_WAIT1();
    __syncthreads();

    for (int ck = 0; ck < 16; ck++) {
        if (ck + 2 < 16) stage_load((ck + 2) % 3, (ck + 2) * 64);
        CP_COMMIT();

        const uint32_t sb = sbase + (uint32_t)(ck % 3) * STAGE_B;
        const uint32_t xs = sb, ws = sb + ARR_B;

#pragma unroll
        for (int ks = 0; ks < 4; ks++) {
            const int kb = ks * 32;
            uint32_t bf[8][2];
#pragma unroll
            for (int pi = 0; pi < 4; pi++) {
                uint32_t boff =
                    (uint32_t)(wn * 64 + pi * 16 + b4_row) * PST + kb + b4_colb;
                ldsm_x4(bf[2 * pi][0], bf[2 * pi][1],
                        bf[2 * pi + 1][0], bf[2 * pi + 1][1], ws + boff);
            }
#pragma unroll
            for (int mi = 0; mi < 2; mi++) {
                uint32_t aoff =
                    (uint32_t)(wm * 32 + mi * 16 + a_row_in) * PST + kb + a_colb;
                uint32_t af[4];
                ldsm_x4(af[0], af[1], af[2], af[3], xs + aoff);
#pragma unroll
                for (int ni = 0; ni < 8; ni++) mma16816(acc[mi][ni], af, bf[ni]);
            }
        }
        CP_WAIT1();
        __syncthreads();
    }

    const int qr = lane >> 2;
    const int qc = (lane & 3) * 2;
    const int L = 1 << Lsh, Lm = L - 1;
#pragma unroll
    for (int mi = 0; mi < 2; mi++) {
#pragma unroll
        for (int rh = 0; rh < 2; rh++) {
            int m = m0 + wm * 32 + mi * 16 + qr + rh * 8;
            int bb = m >> Lsh, l = m & Lm;
#pragma unroll
            for (int ni = 0; ni < 8; ni++) {
                int n = n0 + wn * 64 + ni * 8 + qc;
                int hh = n >> 6, d0 = n & 63;
                float ox = (acc[mi][ni][rh * 2 + 0] + bias[n]) * scale;
                float oy = (acc[mi][ni][rh * 2 + 1] + bias[n + 1]) * scale;
                size_t off = (((size_t)bb * H + hh) * (size_t)L + l) * DH + d0;
                *(uint32_t*)(o + off) = pkhf(ox, oy);
            }
        }
    }
}

// =====================================================================
// Fused attention: pure fp16, fp16 edge, CT=64, double-buffered
// cp.async pipeline, exp2 softmax.
// Stage: K 0 (64x144), V 9216 (64x144), E 18432 (128 x 144B fp16).
// =====================================================================
#define AST 144
#define STG0 18432
#define STG_SZ 36864
#define ATTN_SMEM_BYTES (STG0 + 2 * STG_SZ)   // 92160

__global__ void __launch_bounds__(256, 2) attn_mma(
    const __half* __restrict__ q, const __half* __restrict__ k,
    const __half* __restrict__ v,
    const __half* __restrict__ ed, float* __restrict__ ctx)
{
    extern __shared__ char smem[];
    const uint32_t sbase = smem_u32(smem);
    const int tid = threadIdx.x;
    const int wid = tid >> 5, lane = tid & 31;
    const int b = blockIdx.z, h = blockIdx.y;
    const int p0 = blockIdx.x * 128;

    const size_t qoff = (((size_t)b * H + h) * P + p0) * DH;
    const size_t koff = (((size_t)b * H + h) * C) * DH;
    const __half* ebase = ed + ((size_t)b * P + p0) * C;

    auto load_chunk = [&](uint32_t stg, int cn) {
#pragma unroll
        for (int i = 0; i < 2; i++) {
            int idx = tid + i * 256;
            int row = idx >> 3, seg = idx & 7;
            cp16(stg + row * AST + seg * 16,
                 k + koff + (size_t)(cn + row) * DH + seg * 8);
            cp16(stg + 9216 + row * AST + seg * 16,
                 v + koff + (size_t)(cn + row) * DH + seg * 8);
        }
#pragma unroll
        for (int i = 0; i < 4; i++) {
            int idx = tid + i * 256;
            int er = idx >> 3, seg = idx & 7;
            cp16(stg + 18432 + er * AST + seg * 16,
                 ebase + (size_t)er * C + cn + seg * 8);
        }
    };

    // prologue: Q + chunk 0
#pragma unroll
    for (int i = 0; i < 4; i++) {
        int g = tid + i * 256;
        int row = g >> 3, seg = g & 7;
        cp16(sbase + row * AST + seg * 16,
             q + qoff + (size_t)row * DH + seg * 8);
    }
    load_chunk(sbase + STG0, 0);
    CP_COMMIT();

    const int a_row = (lane & 7) + 8 * ((lane >> 3) & 1);
    const int a_colb = (lane >> 4) * 16;
    const int b4_row = ((lane >> 4) & 1) * 8 + (lane & 7);
    const int b4_colb = ((lane >> 3) & 1) * 16;
    const int r0 = lane >> 2;
    const int wr = wid * 16;
    const int c2 = (lane & 3) * 2;

    CP_WAIT0();
    __syncthreads();

    uint32_t qf[4][4];
#pragma unroll
    for (int ks = 0; ks < 4; ks++) {
        uint32_t aoff = (uint32_t)(wr + a_row) * AST + a_colb + ks * 32;
        ldsm_x4(qf[ks][0], qf[ks][1], qf[ks][2], qf[ks][3], sbase + aoff);
    }

    float m_r[2] = {-1e30f, -1e30f};
    float l_r[2] = {0.f, 0.f};
    float cacc[8][4];
#pragma unroll
    for (int i = 0; i < 8; i++)
#pragma unroll
        for (int j = 0; j < 4; j++) cacc[i][j] = 0.f;

    for (int ck = 0; ck < 8; ck++) {
        const uint32_t stgoff = STG0 + (uint32_t)(ck & 1) * STG_SZ;
        const uint32_t stg = sbase + stgoff;

        if (ck < 7) {
            load_chunk(sbase + STG0 + (uint32_t)((ck + 1) & 1) * STG_SZ,
                       (ck + 1) * 64);
            CP_COMMIT();
        }

        // ---- S = Q K^T : 128p x 64c per CTA, 8 n-tiles per warp ----
        float s[8][4];
#pragma unroll
        for (int i = 0; i < 8; i++)
#pragma unroll
            for (int j = 0; j < 4; j++) s[i][j] = 0.f;

#pragma unroll
        for (int ks = 0; ks < 4; ks++) {
            uint32_t bf[8][2];
#pragma unroll
            for (int pi = 0; pi < 4; pi++) {
                uint32_t boff =
                    (uint32_t)(pi * 16 + b4_row) * AST + b4_colb + ks * 32;
                ldsm_x4(bf[2 * pi][0], bf[2 * pi][1],
                        bf[2 * pi + 1][0], bf[2 * pi + 1][1], stg + boff);
            }
#pragma unroll
            for (int ni = 0; ni < 8; ni++) mma16816(s[ni], qf[ks], bf[ni]);
        }

        // ---- online softmax (exp2 domain, fp16 edge, 64 cols) ----
        float alpha[2];
#pragma unroll
        for (int rr = 0; rr < 2; rr++) {
            const __half* ep = (const __half*)(smem + stgoff + 18432 +
                                (size_t)(wr + r0 + rr * 8) * AST) + c2;
            float ev[8][2];
            float mx = -1e30f;
#pragma unroll
            for (int j = 0; j < 8; j++) {
                float2 e2 = __half22float2(*(const __half2*)(ep + j * 8));
                ev[j][0] = e2.x; ev[j][1] = e2.y;
                float s0 = (e2.x > 0.f) ? s[j][rr * 2] : -1e30f;
                float s1 = (e2.y > 0.f) ? s[j][rr * 2 + 1] : -1e30f;
                s[j][rr * 2] = s0; s[j][rr * 2 + 1] = s1;
                mx = fmaxf(mx, fmaxf(s0, s1));
            }
            mx = fmaxf(mx, __shfl_xor_sync(0xffffffffu, mx, 1));
            mx = fmaxf(mx, __shfl_xor_sync(0xffffffffu, mx, 2));
            float mn = fmaxf(m_r[rr], mx);
            alpha[rr] = exp2r(m_r[rr] - mn);
            m_r[rr] = mn;
            float ls = 0.f;
#pragma unroll
            for (int j = 0; j < 8; j++) {
                float ex0 = exp2r(s[j][rr * 2] - mn);
                float ex1 = exp2r(s[j][rr * 2 + 1] - mn);
                ls += ex0 + ex1;
                s[j][rr * 2] = ex0 * ev[j][0];
                s[j][rr * 2 + 1] = ex1 * ev[j][1];
            }
            ls += __shfl_xor_sync(0xffffffffu, ls, 1);
            ls += __shfl_xor_sync(0xffffffffu, ls, 2);
            l_r[rr] = l_r[rr] * alpha[rr] + ls;
        }

        // ---- rescale ctx, then ctx += P V (4 k-steps of 16 c) ----
#pragma unroll
        for (int ni = 0; ni < 8; ni++) {
            cacc[ni][0] *= alpha[0]; cacc[ni][1] *= alpha[0];
            cacc[ni][2] *= alpha[1]; cacc[ni][3] *= alpha[1];
        }
#pragma unroll
        for (int ks = 0; ks < 4; ks++) {
            const float* t0 = s[2 * ks];
            const float* t1 = s[2 * ks + 1];
            uint32_t ap[4];
            ap[0] = pkhf(t0[0], t0[1]);
            ap[1] = pkhf(t0[2], t0[3]);
            ap[2] = pkhf(t1[0], t1[1]);
            ap[3] = pkhf(t1[2], t1[3]);
            uint32_t vrow = (uint32_t)(ks * 16 + (lane & 15)) * AST;
            uint32_t vf[8][2];
#pragma unroll
            for (int ni = 0; ni < 8; ni++)
                ldsm_x2t(vf[ni][0], vf[ni][1], stg + 9216 + vrow + ni * 16);
#pragma unroll
            for (int ni = 0; ni < 8; ni++) mma16816(cacc[ni], ap, vf[ni]);
        }

        if (ck < 7) {
            CP_WAIT0();
            __syncthreads();
        }
    }

    const float inv0 = 1.0f / l_r[0];
    const float inv1 = 1.0f / l_r[1];
    const int row0 = p0 + wr + r0;
#pragma unroll
    for (int ni = 0; ni < 8; ni++) {
        int dh = ni * 8 + c2;
        size_t base0 = ((size_t)b * P + row0) * D + h * DH + dh;
        float2 o0{cacc[ni][0] * inv0, cacc[ni][1] * inv0};
        float2 o1{cacc[ni][2] * inv1, cacc[ni][3] * inv1};
        *(float2*)(ctx + base0) = o0;
        *(float2*)(ctx + base0 + (size_t)8 * D) = o1;
    }
}

// =====================================================================
// LayerNorm over D=1024: 2 rows per block (MLP=2, shared gamma/beta).
// =====================================================================
__global__ void __launch_bounds__(256) ln_kernel(
    const float* __restrict__ x, const float* __restrict__ gamma,
    const float* __restrict__ beta, float* __restrict__ out)
{
    __shared__ float rs1[2][8], rs2[2][8];
    const size_t row0 = (size_t)blockIdx.x * 2;
    const int tid = threadIdx.x;
    const float4 xa = *(const float4*)(x + row0 * D + tid * 4);
    const float4 xb = *(const float4*)(x + (row0 + 1) * D + tid * 4);
    float a1 = xa.x + xa.y + xa.z + xa.w;
    float a2 = xa.x * xa.x + xa.y * xa.y + xa.z * xa.z + xa.w * xa.w;
    float b1 = xb.x + xb.y + xb.z + xb.w;
    float b2 = xb.x * xb.x + xb.y * xb.y + xb.z * xb.z + xb.w * xb.w;
#pragma unroll
    for (int o = 16; o; o >>= 1) {
        a1 += __shfl_xor_sync(0xffffffffu, a1, o);
        a2 += __shfl_xor_sync(0xffffffffu, a2, o);
        b1 += __shfl_xor_sync(0xffffffffu, b1, o);
        b2 += __shfl_xor_sync(0xffffffffu, b2, o);
    }
    if ((tid & 31) == 0) {
        rs1[0][tid >> 5] = a1; rs2[0][tid >> 5] = a2;
        rs1[1][tid >> 5] = b1; rs2[1][tid >> 5] = b2;
    }
    __syncthreads();
    if (tid < 32) {
        float t1 = (tid < 8) ? rs1[0][tid] : 0.f;
        float t2 = (tid < 8) ? rs2[0][tid] : 0.f;
        float u1 = (tid < 8) ? rs1[1][tid] : 0.f;
        float u2 = (tid < 8) ? rs2[1][tid] : 0.f;
#pragma unroll
        for (int o = 4; o; o >>= 1) {
            t1 += __shfl_xor_sync(0xffffffffu, t1, o);
            t2 += __shfl_xor_sync(0xffffffffu, t2, o);
            u1 += __shfl_xor_sync(0xffffffffu, u1, o);
            u2 += __shfl_xor_sync(0xffffffffu, u2, o);
        }
        if (tid == 0) {
            rs1[0][0] = t1; rs2[0][0] = t2;
            rs1[1][0] = u1; rs2[1][0] = u2;
        }
    }
    __syncthreads();
    const float4 g = *(const float4*)(gamma + tid * 4);
    const float4 bt = *(const float4*)(beta + tid * 4);

    const float mua = rs1[0][0] * (1.0f / D);
    const float vara = fmaxf(rs2[0][0] * (1.0f / D) - mua * mua, 0.f);
    const float ra = rsqrtf(vara + 1e-6f);
    float4 oa;
    oa.x = (xa.x - mua) * ra * g.x + bt.x;
    oa.y = (xa.y - mua) * ra * g.y + bt.y;
    oa.z = (xa.z - mua) * ra * g.z + bt.z;
    oa.w = (xa.w - mua) * ra * g.w + bt.w;
    *(float4*)(out + row0 * D + tid * 4) = oa;

    const float mub = rs1[1][0] * (1.0f / D);
    const float varb = fmaxf(rs2[1][0] * (1.0f / D) - mub * mub, 0.f);
    const float rb = rsqrtf(varb + 1e-6f);
    float4 ob;
    ob.x = (xb.x - mub) * rb * g.x + bt.x;
    ob.y = (xb.y - mub) * rb * g.y + bt.y;
    ob.z = (xb.z - mub) * rb * g.z + bt.z;
    ob.w = (xb.w - mub) * rb * g.w + bt.w;
    *(float4*)(out + (row0 + 1) * D + tid * 4) = ob;
}

// =====================================================================
extern "C" void kernel_launch(void* const* d_in, const int* in_sizes, int n_in,
                              void* d_out, int out_size)
{
    const float* para    = (const float*)d_in[0];
    const float* cluster = (const float*)d_in[1];
    const float* edge    = (const float*)d_in[2];
    const float* Wq = (const float*)d_in[3];
    const float* bq = (const float*)d_in[4];
    const float* Wk = (const float*)d_in[5];
    const float* bk = (const float*)d_in[6];
    const float* Wv = (const float*)d_in[7];
    const float* bv = (const float*)d_in[8];
    const float* gamma = (const float*)d_in[9];
    const float* beta  = (const float*)d_in[10];
    float* out = (float*)d_out;

    float* cp;
    __half *qp, *kp, *vp, *pap, *clp, *wtp, *edp;
    cudaGetSymbolAddress((void**)&cp, g_ctx);
    cudaGetSymbolAddress((void**)&qp, g_q);
    cudaGetSymbolAddress((void**)&kp, g_k);
    cudaGetSymbolAddress((void**)&vp, g_v);
    cudaGetSymbolAddress((void**)&pap, g_pa);
    cudaGetSymbolAddress((void**)&clp, g_cl);
    cudaGetSymbolAddress((void**)&wtp, g_wt);
    cudaGetSymbolAddress((void**)&edp, g_ed);

    cudaFuncSetAttribute(proj_mma,
                         cudaFuncAttributeMaxDynamicSharedMemorySize,
                         PROJ_SMEM_BYTES);
    cudaFuncSetAttribute(attn_mma,
                         cudaFuncAttributeMaxDynamicSharedMemorySize,
                         ATTN_SMEM_BYTES);

    prep_all<<<PREP_BLKS, 256>>>(para, cluster, edge, Wq, Wk, Wv,
                                 pap, clp, edp, wtp);

    proj_mma<<<768, 256, PROJ_SMEM_BYTES>>>(pap, clp, wtp, bq, bk, bv,
                                            qp, kp, vp);

    attn_mma<<<dim3(P / 128, H, B), 256, ATTN_SMEM_BYTES>>>(
        qp, kp, vp, edp, cp);

    ln_kernel<<<(B * P) / 2, 256>>>(cp, gamma, beta, out);
}

// round 14
// speedup vs baseline: 1.0287x; 1.0147x over previous
#include <cuda_runtime.h>
#include <cuda_fp16.h>
#include <math.h>
#include <stdint.h>

#define B 4
#define P 2048
#define C 512
#define D 1024
#define H 16
#define DH 64

// ---------------- scratch (static device arrays) ----------------
__device__ __half g_q[(size_t)B * H * P * DH];
__device__ __half g_k[(size_t)B * H * C * DH];
__device__ __half g_v[(size_t)B * H * C * DH];
__device__ float g_ctx[(size_t)B * P * D];
__device__ __half g_pa[(size_t)B * P * D];
__device__ __half g_cl[(size_t)B * C * D];
__device__ __half g_wt[(size_t)3 * D * D];
__device__ __half g_ed[(size_t)B * P * C];

__device__ __forceinline__ uint32_t smem_u32(const void* p) {
    uint32_t a;
    asm("{ .reg .u64 t; cvta.to.shared.u64 t, %1; cvt.u32.u64 %0, t; }"
        : "=r"(a) : "l"(p));
    return a;
}

// ---------------- mma.sync helpers (fp16 in, fp32 accum) ----------------
__device__ __forceinline__ void ldsm_x4(uint32_t& r0, uint32_t& r1,
                                        uint32_t& r2, uint32_t& r3, uint32_t a) {
    asm volatile("ldmatrix.sync.aligned.m8n8.x4.shared.b16 {%0,%1,%2,%3}, [%4];"
                 : "=r"(r0), "=r"(r1), "=r"(r2), "=r"(r3) : "r"(a));
}
__device__ __forceinline__ void ldsm_x2t(uint32_t& r0, uint32_t& r1, uint32_t a) {
    asm volatile("ldmatrix.sync.aligned.m8n8.x2.trans.shared.b16 {%0,%1}, [%2];"
                 : "=r"(r0), "=r"(r1) : "r"(a));
}
__device__ __forceinline__ void mma16816(float* d, const uint32_t* a,
                                         const uint32_t* b) {
    asm volatile(
        "mma.sync.aligned.m16n8k16.row.col.f32.f16.f16.f32 "
        "{%0,%1,%2,%3}, {%4,%5,%6,%7}, {%8,%9}, {%0,%1,%2,%3};"
        : "+f"(d[0]), "+f"(d[1]), "+f"(d[2]), "+f"(d[3])
        : "r"(a[0]), "r"(a[1]), "r"(a[2]), "r"(a[3]), "r"(b[0]), "r"(b[1]));
}
__device__ __forceinline__ void cp16(uint32_t dst, const void* src) {
    asm volatile("cp.async.cg.shared.global [%0], [%1], 16;"
                 :: "r"(dst), "l"(src));
}
#define CP_COMMIT() asm volatile("cp.async.commit_group;" ::: "memory")
#define CP_WAIT0()  asm volatile("cp.async.wait_group 0;" ::: "memory")
#define CP_WAIT1()  asm volatile("cp.async.wait_group 1;" ::: "memory")

// pack two f32 -> f16x2 (first arg in LOW half)
__device__ __forceinline__ uint32_t pkhf(float lo, float hi) {
    uint32_t d;
    asm("cvt.rn.f16x2.f32 %0, %1, %2;" : "=r"(d) : "f"(hi), "f"(lo));
    return d;
}
__device__ __forceinline__ float exp2r(float x) {
    float y; asm("ex2.approx.ftz.f32 %0, %1;" : "=f"(y) : "f"(x)); return y;
}

// =====================================================================
// Merged prep: fp16 converts with MLP=4 (4 float4 loads in flight per
// thread) | W transpose fp16.
// =====================================================================
#define CVT_CHUNK 4096
#define PA_BLKS ((B * P * D) / CVT_CHUNK)   // 2048
#define CL_BLKS ((B * C * D) / CVT_CHUNK)   // 512
#define ED_BLKS ((B * P * C) / CVT_CHUNK)   // 1024
#define WT_BLKS (32 * 32 * 3)               // 3072
#define PREP_BLKS (PA_BLKS + CL_BLKS + ED_BLKS + WT_BLKS)

__global__ void __launch_bounds__(256) prep_all(
    const float* __restrict__ para, const float* __restrict__ cluster,
    const float* __restrict__ edge,
    const float* __restrict__ Wq, const float* __restrict__ Wk,
    const float* __restrict__ Wv,
    __half* __restrict__ pa, __half* __restrict__ cl,
    __half* __restrict__ ed, __half* __restrict__ wt)
{
    const int bid = blockIdx.x;
    if (bid < PA_BLKS + CL_BLKS + ED_BLKS) {
        const float* x;
        __half* o;
        size_t base;
        if (bid < PA_BLKS) { x = para; o = pa; base = (size_t)bid * CVT_CHUNK; }
        else if (bid < PA_BLKS + CL_BLKS) {
            x = cluster; o = cl; base = (size_t)(bid - PA_BLKS) * CVT_CHUNK;
        } else {
            x = edge; o = ed; base = (size_t)(bid - PA_BLKS - CL_BLKS) * CVT_CHUNK;
        }
        const size_t i0 = base + (size_t)threadIdx.x * 4;
        // 4 independent loads in flight (MLP=4)
        float4 v0 = *(const float4*)(x + i0);
        float4 v1 = *(const float4*)(x + i0 + 1024);
        float4 v2 = *(const float4*)(x + i0 + 2048);
        float4 v3 = *(const float4*)(x + i0 + 3072);
#define CVT_STORE(v, off)                                                      \
        do {                                                                   \
            __half2 p0{__float2half_rn((v).x), __float2half_rn((v).y)};        \
            __half2 p1{__float2half_rn((v).z), __float2half_rn((v).w)};        \
            *(__half2*)(o + i0 + (off)) = p0;                                  \
            *(__half2*)(o + i0 + (off) + 2) = p1;                              \
        } while (0)
        CVT_STORE(v0, 0);
        CVT_STORE(v1, 1024);
        CVT_STORE(v2, 2048);
        CVT_STORE(v3, 3072);
#undef CVT_STORE
        return;
    }
    __shared__ float t[32][33];
    const int wb = bid - PA_BLKS - CL_BLKS - ED_BLKS;
    const int wz = wb >> 10;
    const int rem = wb & 1023;
    const int kb = (rem & 31) * 32, nb = (rem >> 5) * 32;
    const float* W = (wz == 0) ? Wq : (wz == 1) ? Wk : Wv;
    size_t ooff = (size_t)wz * D * D;
    int tx = threadIdx.x & 31, ty = threadIdx.x >> 5;
#pragma unroll
    for (int j = 0; j < 4; j++)
        t[ty + j * 8][tx] = W[(size_t)(kb + ty + j * 8) * D + nb + tx];
    __syncthreads();
#pragma unroll
    for (int j = 0; j < 4; j++) {
        int n = nb + ty + j * 8, kk = kb + tx;
        wt[ooff + (size_t)n * D + kk] = __float2half_rn(t[tx][ty + j * 8]);
    }
}

// =====================================================================
// Projection GEMM: pure fp16 single-pass, 3-stage cp.async ring,
// warp grid 4(m) x 2(n), K chunks of 64.  (unchanged)
// =====================================================================
#define PST 144
#define ARR_B (128 * PST)
#define STAGE_B (2 * ARR_B)
#define PROJ_SMEM_BYTES (3 * STAGE_B)

__global__ void __launch_bounds__(256, 2) proj_mma(
    const __half* __restrict__ pa, const __half* __restrict__ cl,
    const __half* __restrict__ wt,
    const float* __restrict__ bq, const float* __restrict__ bk,
    const float* __restrict__ bv,
    __half* __restrict__ q, __half* __restrict__ k, __half* __restrict__ v)
{
    extern __shared__ char smem[];
    const uint32_t sbase = smem_u32(smem);
    const int tid = threadIdx.x;
    const int wid = tid >> 5, lane = tid & 31;

    const int bid = blockIdx.x;
    const __half *X, *W;
    const float* bias;
    __half* o;
    int mblk, Lsh; float scale;
    if (bid < 512) {
        X = pa; W = wt;
        bias = bq; o = q; Lsh = 11;
        scale = 0.125f * 1.44269504f;
        mblk = bid >> 3;
    } else if (bid < 640) {
        X = cl; W = wt + (size_t)D * D;
        bias = bk; o = k; Lsh = 9; scale = 1.0f;
        mblk = (bid - 512) >> 3;
    } else {
        X = cl; W = wt + (size_t)2 * D * D;
        bias = bv; o = v; Lsh = 9; scale = 1.0f;
        mblk = (bid - 640) >> 3;
    }
    const int n0 = (bid & 7) * 128;
    const int m0 = mblk * 128;

    const int wm = wid >> 1, wn = wid & 1;

    auto stage_load = [&](int stg, int k0) {
        const uint32_t sb = sbase + (uint32_t)stg * STAGE_B;
        const __half* srcs[2] = {X, W};
        const int rowoff[2] = {m0, n0};
#pragma unroll
        for (int a = 0; a < 2; a++) {
            const __half* s = srcs[a];
            uint32_t ab = sb + a * ARR_B;
#pragma unroll
            for (int i = 0; i < 4; i++) {
                int idx = tid + i * 256;
                int row = idx >> 3, seg = idx & 7;
                cp16(ab + row * PST + seg * 16,
                     s + (size_t)(rowoff[a] + row) * D + k0 + seg * 8);
            }
        }
    };

    float acc[2][8][4];
#pragma unroll
    for (int i = 0; i < 2; i++)
#pragma unroll
        for (int j = 0; j < 8; j++)
#pragma unroll
            for (int qq = 0; qq < 4; qq++) acc[i][j][qq] = 0.f;

    const int a_row_in = (lane & 7) + 8 * ((lane >> 3) & 1);
    const int a_colb = (lane >> 4) * 16;
    const int b4_row = ((lane >> 4) & 1) * 8 + (lane & 7);
    const int b4_colb = ((lane >> 3) & 1) * 16;

    stage_load(0, 0);
    CP_COMMIT();
    stage_load(1, 64);
    CP_COMMIT();
    CP_WAIT1();
    __syncthreads();

    for (int ck = 0; ck < 16; ck++) {
        if (ck + 2 < 16) stage_load((ck + 2) % 3, (ck + 2) * 64);
        CP_COMMIT();

        const uint32_t sb = sbase + (uint32_t)(ck % 3) * STAGE_B;
        const uint32_t xs = sb, ws = sb + ARR_B;

#pragma unroll
        for (int ks = 0; ks < 4; ks++) {
            const int kb = ks * 32;
            uint32_t bf[8][2];
#pragma unroll
            for (int pi = 0; pi < 4; pi++) {
                uint32_t boff =
                    (uint32_t)(wn * 64 + pi * 16 + b4_row) * PST + kb + b4_colb;
                ldsm_x4(bf[2 * pi][0], bf[2 * pi][1],
                        bf[2 * pi + 1][0], bf[2 * pi + 1][1], ws + boff);
            }
#pragma unroll
            for (int mi = 0; mi < 2; mi++) {
                uint32_t aoff =
                    (uint32_t)(wm * 32 + mi * 16 + a_row_in) * PST + kb + a_colb;
                uint32_t af[4];
                ldsm_x4(af[0], af[1], af[2], af[3], xs + aoff);
#pragma unroll
                for (int ni = 0; ni < 8; ni++) mma16816(acc[mi][ni], af, bf[ni]);
            }
        }
        CP_WAIT1();
        __syncthreads();
    }

    const int qr = lane >> 2;
    const int qc = (lane & 3) * 2;
    const int L = 1 << Lsh, Lm = L - 1;
#pragma unroll
    for (int mi = 0; mi < 2; mi++) {
#pragma unroll
        for (int rh = 0; rh < 2; rh++) {
            int m = m0 + wm * 32 + mi * 16 + qr + rh * 8;
            int bb = m >> Lsh, l = m & Lm;
#pragma unroll
            for (int ni = 0; ni < 8; ni++) {
                int n = n0 + wn * 64 + ni * 8 + qc;
                int hh = n >> 6, d0 = n & 63;
                float ox = (acc[mi][ni][rh * 2 + 0] + bias[n]) * scale;
                float oy = (acc[mi][ni][rh * 2 + 1] + bias[n + 1]) * scale;
                size_t off = (((size_t)bb * H + hh) * (size_t)L + l) * DH + d0;
                *(uint32_t*)(o + off) = pkhf(ox, oy);
            }
        }
    }
}

// =====================================================================
// Fused attention: pure fp16, fp16 edge, CT=64, double-buffered
// cp.async pipeline, exp2 softmax.  (unchanged)
// =====================================================================
#define AST 144
#define STG0 18432
#define STG_SZ 36864
#define ATTN_SMEM_BYTES (STG0 + 2 * STG_SZ)

__global__ void __launch_bounds__(256, 2) attn_mma(
    const __half* __restrict__ q, const __half* __restrict__ k,
    const __half* __restrict__ v,
    const __half* __restrict__ ed, float* __restrict__ ctx)
{
    extern __shared__ char smem[];
    const uint32_t sbase = smem_u32(smem);
    const int tid = threadIdx.x;
    const int wid = tid >> 5, lane = tid & 31;
    const int b = blockIdx.z, h = blockIdx.y;
    const int p0 = blockIdx.x * 128;

    const size_t qoff = (((size_t)b * H + h) * P + p0) * DH;
    const size_t koff = (((size_t)b * H + h) * C) * DH;
    const __half* ebase = ed + ((size_t)b * P + p0) * C;

    auto load_chunk = [&](uint32_t stg, int cn) {
#pragma unroll
        for (int i = 0; i < 2; i++) {
            int idx = tid + i * 256;
            int row = idx >> 3, seg = idx & 7;
            cp16(stg + row * AST + seg * 16,
                 k + koff + (size_t)(cn + row) * DH + seg * 8);
            cp16(stg + 9216 + row * AST + seg * 16,
                 v + koff + (size_t)(cn + row) * DH + seg * 8);
        }
#pragma unroll
        for (int i = 0; i < 4; i++) {
            int idx = tid + i * 256;
            int er = idx >> 3, seg = idx & 7;
            cp16(stg + 18432 + er * AST + seg * 16,
                 ebase + (size_t)er * C + cn + seg * 8);
        }
    };

#pragma unroll
    for (int i = 0; i < 4; i++) {
        int g = tid + i * 256;
        int row = g >> 3, seg = g & 7;
        cp16(sbase + row * AST + seg * 16,
             q + qoff + (size_t)row * DH + seg * 8);
    }
    load_chunk(sbase + STG0, 0);
    CP_COMMIT();

    const int a_row = (lane & 7) + 8 * ((lane >> 3) & 1);
    const int a_colb = (lane >> 4) * 16;
    const int b4_row = ((lane >> 4) & 1) * 8 + (lane & 7);
    const int b4_colb = ((lane >> 3) & 1) * 16;
    const int r0 = lane >> 2;
    const int wr = wid * 16;
    const int c2 = (lane & 3) * 2;

    CP_WAIT0();
    __syncthreads();

    uint32_t qf[4][4];
#pragma unroll
    for (int ks = 0; ks < 4; ks++) {
        uint32_t aoff = (uint32_t)(wr + a_row) * AST + a_colb + ks * 32;
        ldsm_x4(qf[ks][0], qf[ks][1], qf[ks][2], qf[ks][3], sbase + aoff);
    }

    float m_r[2] = {-1e30f, -1e30f};
    float l_r[2] = {0.f, 0.f};
    float cacc[8][4];
#pragma unroll
    for (int i = 0; i < 8; i++)
#pragma unroll
        for (int j = 0; j < 4; j++) cacc[i][j] = 0.f;

    for (int ck = 0; ck < 8; ck++) {
        const uint32_t stgoff = STG0 + (uint32_t)(ck & 1) * STG_SZ;
        const uint32_t stg = sbase + stgoff;

        if (ck < 7) {
            load_chunk(sbase + STG0 + (uint32_t)((ck + 1) & 1) * STG_SZ,
                       (ck + 1) * 64);
            CP_COMMIT();
        }

        float s[8][4];
#pragma unroll
        for (int i = 0; i < 8; i++)
#pragma unroll
            for (int j = 0; j < 4; j++) s[i][j] = 0.f;

#pragma unroll
        for (int ks = 0; ks < 4; ks++) {
            uint32_t bf[8][2];
#pragma unroll
            for (int pi = 0; pi < 4; pi++) {
                uint32_t boff =
                    (uint32_t)(pi * 16 + b4_row) * AST + b4_colb + ks * 32;
                ldsm_x4(bf[2 * pi][0], bf[2 * pi][1],
                        bf[2 * pi + 1][0], bf[2 * pi + 1][1], stg + boff);
            }
#pragma unroll
            for (int ni = 0; ni < 8; ni++) mma16816(s[ni], qf[ks], bf[ni]);
        }

        float alpha[2];
#pragma unroll
        for (int rr = 0; rr < 2; rr++) {
            const __half* ep = (const __half*)(smem + stgoff + 18432 +
                                (size_t)(wr + r0 + rr * 8) * AST) + c2;
            float ev[8][2];
            float mx = -1e30f;
#pragma unroll
            for (int j = 0; j < 8; j++) {
                float2 e2 = __half22float2(*(const __half2*)(ep + j * 8));
                ev[j][0] = e2.x; ev[j][1] = e2.y;
                float s0 = (e2.x > 0.f) ? s[j][rr * 2] : -1e30f;
                float s1 = (e2.y > 0.f) ? s[j][rr * 2 + 1] : -1e30f;
                s[j][rr * 2] = s0; s[j][rr * 2 + 1] = s1;
                mx = fmaxf(mx, fmaxf(s0, s1));
            }
            mx = fmaxf(mx, __shfl_xor_sync(0xffffffffu, mx, 1));
            mx = fmaxf(mx, __shfl_xor_sync(0xffffffffu, mx, 2));
            float mn = fmaxf(m_r[rr], mx);
            alpha[rr] = exp2r(m_r[rr] - mn);
            m_r[rr] = mn;
            float ls = 0.f;
#pragma unroll
            for (int j = 0; j < 8; j++) {
                float ex0 = exp2r(s[j][rr * 2] - mn);
                float ex1 = exp2r(s[j][rr * 2 + 1] - mn);
                ls += ex0 + ex1;
                s[j][rr * 2] = ex0 * ev[j][0];
                s[j][rr * 2 + 1] = ex1 * ev[j][1];
            }
            ls += __shfl_xor_sync(0xffffffffu, ls, 1);
            ls += __shfl_xor_sync(0xffffffffu, ls, 2);
            l_r[rr] = l_r[rr] * alpha[rr] + ls;
        }

#pragma unroll
        for (int ni = 0; ni < 8; ni++) {
            cacc[ni][0] *= alpha[0]; cacc[ni][1] *= alpha[0];
            cacc[ni][2] *= alpha[1]; cacc[ni][3] *= alpha[1];
        }
#pragma unroll
        for (int ks = 0; ks < 4; ks++) {
            const float* t0 = s[2 * ks];
            const float* t1 = s[2 * ks + 1];
            uint32_t ap[4];
            ap[0] = pkhf(t0[0], t0[1]);
            ap[1] = pkhf(t0[2], t0[3]);
            ap[2] = pkhf(t1[0], t1[1]);
            ap[3] = pkhf(t1[2], t1[3]);
            uint32_t vrow = (uint32_t)(ks * 16 + (lane & 15)) * AST;
            uint32_t vf[8][2];
#pragma unroll
            for (int ni = 0; ni < 8; ni++)
                ldsm_x2t(vf[ni][0], vf[ni][1], stg + 9216 + vrow + ni * 16);
#pragma unroll
            for (int ni = 0; ni < 8; ni++) mma16816(cacc[ni], ap, vf[ni]);
        }

        if (ck < 7) {
            CP_WAIT0();
            __syncthreads();
        }
    }

    const float inv0 = 1.0f / l_r[0];
    const float inv1 = 1.0f / l_r[1];
    const int row0 = p0 + wr + r0;
#pragma unroll
    for (int ni = 0; ni < 8; ni++) {
        int dh = ni * 8 + c2;
        size_t base0 = ((size_t)b * P + row0) * D + h * DH + dh;
        float2 o0{cacc[ni][0] * inv0, cacc[ni][1] * inv0};
        float2 o1{cacc[ni][2] * inv1, cacc[ni][3] * inv1};
        *(float2*)(ctx + base0) = o0;
        *(float2*)(ctx + base0 + (size_t)8 * D) = o1;
    }
}

// =====================================================================
// LayerNorm over D=1024: 4 rows per block (MLP=4, shared gamma/beta).
// =====================================================================
__global__ void __launch_bounds__(256) ln_kernel(
    const float* __restrict__ x, const float* __restrict__ gamma,
    const float* __restrict__ beta, float* __restrict__ out)
{
    __shared__ float rs1[4][8], rs2[4][8];
    const size_t row0 = (size_t)blockIdx.x * 4;
    const int tid = threadIdx.x;
    float4 xv[4];
#pragma unroll
    for (int r = 0; r < 4; r++)
        xv[r] = *(const float4*)(x + (row0 + r) * D + tid * 4);

    float s1[4], s2[4];
#pragma unroll
    for (int r = 0; r < 4; r++) {
        s1[r] = xv[r].x + xv[r].y + xv[r].z + xv[r].w;
        s2[r] = xv[r].x * xv[r].x + xv[r].y * xv[r].y +
                xv[r].z * xv[r].z + xv[r].w * xv[r].w;
    }
#pragma unroll
    for (int o = 16; o; o >>= 1) {
#pragma unroll
        for (int r = 0; r < 4; r++) {
            s1[r] += __shfl_xor_sync(0xffffffffu, s1[r], o);
            s2[r] += __shfl_xor_sync(0xffffffffu, s2[r], o);
        }
    }
    if ((tid & 31) == 0) {
#pragma unroll
        for (int r = 0; r < 4; r++) {
            rs1[r][tid >> 5] = s1[r];
            rs2[r][tid >> 5] = s2[r];
        }
    }
    __syncthreads();
    if (tid < 32) {
        float t1[4], t2[4];
#pragma unroll
        for (int r = 0; r < 4; r++) {
            t1[r] = (tid < 8) ? rs1[r][tid] : 0.f;
            t2[r] = (tid < 8) ? rs2[r][tid] : 0.f;
        }
#pragma unroll
        for (int o = 4; o; o >>= 1) {
#pragma unroll
            for (int r = 0; r < 4; r++) {
                t1[r] += __shfl_xor_sync(0xffffffffu, t1[r], o);
                t2[r] += __shfl_xor_sync(0xffffffffu, t2[r], o);
            }
        }
        if (tid == 0) {
#pragma unroll
            for (int r = 0; r < 4; r++) {
                rs1[r][0] = t1[r];
                rs2[r][0] = t2[r];
            }
        }
    }
    __syncthreads();
    const float4 g = *(const float4*)(gamma + tid * 4);
    const float4 bt = *(const float4*)(beta + tid * 4);
#pragma unroll
    for (int r = 0; r < 4; r++) {
        const float mu = rs1[r][0] * (1.0f / D);
        const float var = fmaxf(rs2[r][0] * (1.0f / D) - mu * mu, 0.f);
        const float rr = rsqrtf(var + 1e-6f);
        float4 o;
        o.x = (xv[r].x - mu) * rr * g.x + bt.x;
        o.y = (xv[r].y - mu) * rr * g.y + bt.y;
        o.z = (xv[r].z - mu) * rr * g.z + bt.z;
        o.w = (xv[r].w - mu) * rr * g.w + bt.w;
        *(float4*)(out + (row0 + r) * D + tid * 4) = o;
    }
}

// =====================================================================
extern "C" void kernel_launch(void* const* d_in, const int* in_sizes, int n_in,
                              void* d_out, int out_size)
{
    const float* para    = (const float*)d_in[0];
    const float* cluster = (const float*)d_in[1];
    const float* edge    = (const float*)d_in[2];
    const float* Wq = (const float*)d_in[3];
    const float* bq = (const float*)d_in[4];
    const float* Wk = (const float*)d_in[5];
    const float* bk = (const float*)d_in[6];
    const float* Wv = (const float*)d_in[7];
    const float* bv = (const float*)d_in[8];
    const float* gamma = (const float*)d_in[9];
    const float* beta  = (const float*)d_in[10];
    float* out = (float*)d_out;

    float* cp;
    __half *qp, *kp, *vp, *pap, *clp, *wtp, *edp;
    cudaGetSymbolAddress((void**)&cp, g_ctx);
    cudaGetSymbolAddress((void**)&qp, g_q);
    cudaGetSymbolAddress((void**)&kp, g_k);
    cudaGetSymbolAddress((void**)&vp, g_v);
    cudaGetSymbolAddress((void**)&pap, g_pa);
    cudaGetSymbolAddress((void**)&clp, g_cl);
    cudaGetSymbolAddress((void**)&wtp, g_wt);
    cudaGetSymbolAddress((void**)&edp, g_ed);

    cudaFuncSetAttribute(proj_mma,
                         cudaFuncAttributeMaxDynamicSharedMemorySize,
                         PROJ_SMEM_BYTES);
    cudaFuncSetAttribute(attn_mma,
                         cudaFuncAttributeMaxDynamicSharedMemorySize,
                         ATTN_SMEM_BYTES);

    prep_all<<<PREP_BLKS, 256>>>(para, cluster, edge, Wq, Wk, Wv,
                                 pap, clp, edp, wtp);

    proj_mma<<<768, 256, PROJ_SMEM_BYTES>>>(pap, clp, wtp, bq, bk, bv,
                                            qp, kp, vp);

    attn_mma<<<dim3(P / 128, H, B), 256, ATTN_SMEM_BYTES>>>(
        qp, kp, vp, edp, cp);

    ln_kernel<<<(B * P) / 4, 256>>>(cp, gamma, beta, out);
}

// round 15
// speedup vs baseline: 1.0336x; 1.0048x over previous
#include <cuda_runtime.h>
#include <cuda_fp16.h>
#include <math.h>
#include <stdint.h>

#define B 4
#define P 2048
#define C 512
#define D 1024
#define H 16
#define DH 64

// ---------------- scratch (static device arrays) ----------------
__device__ __half g_q[(size_t)B * H * P * DH];
__device__ __half g_k[(size_t)B * H * C * DH];
__device__ __half g_v[(size_t)B * H * C * DH];
__device__ __half g_ctx[(size_t)B * P * D];
__device__ __half g_pa[(size_t)B * P * D];
__device__ __half g_cl[(size_t)B * C * D];
__device__ __half g_wt[(size_t)3 * D * D];
__device__ __half g_ed[(size_t)B * P * C];

__device__ __forceinline__ uint32_t smem_u32(const void* p) {
    uint32_t a;
    asm("{ .reg .u64 t; cvta.to.shared.u64 t, %1; cvt.u32.u64 %0, t; }"
        : "=r"(a) : "l"(p));
    return a;
}

// ---------------- mma.sync helpers (fp16 in, fp32 accum) ----------------
__device__ __forceinline__ void ldsm_x4(uint32_t& r0, uint32_t& r1,
                                        uint32_t& r2, uint32_t& r3, uint32_t a) {
    asm volatile("ldmatrix.sync.aligned.m8n8.x4.shared.b16 {%0,%1,%2,%3}, [%4];"
                 : "=r"(r0), "=r"(r1), "=r"(r2), "=r"(r3) : "r"(a));
}
__device__ __forceinline__ void ldsm_x2t(uint32_t& r0, uint32_t& r1, uint32_t a) {
    asm volatile("ldmatrix.sync.aligned.m8n8.x2.trans.shared.b16 {%0,%1}, [%2];"
                 : "=r"(r0), "=r"(r1) : "r"(a));
}
__device__ __forceinline__ void mma16816(float* d, const uint32_t* a,
                                         const uint32_t* b) {
    asm volatile(
        "mma.sync.aligned.m16n8k16.row.col.f32.f16.f16.f32 "
        "{%0,%1,%2,%3}, {%4,%5,%6,%7}, {%8,%9}, {%0,%1,%2,%3};"
        : "+f"(d[0]), "+f"(d[1]), "+f"(d[2]), "+f"(d[3])
        : "r"(a[0]), "r"(a[1]), "r"(a[2]), "r"(a[3]), "r"(b[0]), "r"(b[1]));
}
__device__ __forceinline__ void cp16(uint32_t dst, const void* src) {
    asm volatile("cp.async.cg.shared.global [%0], [%1], 16;"
                 :: "r"(dst), "l"(src));
}
#define CP_COMMIT() asm volatile("cp.async.commit_group;" ::: "memory")
#define CP_WAIT0()  asm volatile("cp.async.wait_group 0;" ::: "memory")
#define CP_WAIT1()  asm volatile("cp.async.wait_group 1;" ::: "memory")

// pack two f32 -> f16x2 (first arg in LOW half)
__device__ __forceinline__ uint32_t pkhf(float lo, float hi) {
    uint32_t d;
    asm("cvt.rn.f16x2.f32 %0, %1, %2;" : "=r"(d) : "f"(hi), "f"(lo));
    return d;
}
__device__ __forceinline__ float exp2r(float x) {
    float y; asm("ex2.approx.ftz.f32 %0, %1;" : "=f"(y) : "f"(x)); return y;
}

// =====================================================================
// Merged prep: fp16 converts with MLP=4 | W transpose fp16.
// =====================================================================
#define CVT_CHUNK 4096
#define PA_BLKS ((B * P * D) / CVT_CHUNK)
#define CL_BLKS ((B * C * D) / CVT_CHUNK)
#define ED_BLKS ((B * P * C) / CVT_CHUNK)
#define WT_BLKS (32 * 32 * 3)
#define PREP_BLKS (PA_BLKS + CL_BLKS + ED_BLKS + WT_BLKS)

__global__ void __launch_bounds__(256) prep_all(
    const float* __restrict__ para, const float* __restrict__ cluster,
    const float* __restrict__ edge,
    const float* __restrict__ Wq, const float* __restrict__ Wk,
    const float* __restrict__ Wv,
    __half* __restrict__ pa, __half* __restrict__ cl,
    __half* __restrict__ ed, __half* __restrict__ wt)
{
    const int bid = blockIdx.x;
    if (bid < PA_BLKS + CL_BLKS + ED_BLKS) {
        const float* x;
        __half* o;
        size_t base;
        if (bid < PA_BLKS) { x = para; o = pa; base = (size_t)bid * CVT_CHUNK; }
        else if (bid < PA_BLKS + CL_BLKS) {
            x = cluster; o = cl; base = (size_t)(bid - PA_BLKS) * CVT_CHUNK;
        } else {
            x = edge; o = ed; base = (size_t)(bid - PA_BLKS - CL_BLKS) * CVT_CHUNK;
        }
        const size_t i0 = base + (size_t)threadIdx.x * 4;
        float4 v0 = *(const float4*)(x + i0);
        float4 v1 = *(const float4*)(x + i0 + 1024);
        float4 v2 = *(const float4*)(x + i0 + 2048);
        float4 v3 = *(const float4*)(x + i0 + 3072);
#define CVT_STORE(v, off)                                                      \
        do {                                                                   \
            __half2 p0{__float2half_rn((v).x), __float2half_rn((v).y)};        \
            __half2 p1{__float2half_rn((v).z), __float2half_rn((v).w)};        \
            *(__half2*)(o + i0 + (off)) = p0;                                  \
            *(__half2*)(o + i0 + (off) + 2) = p1;                              \
        } while (0)
        CVT_STORE(v0, 0);
        CVT_STORE(v1, 1024);
        CVT_STORE(v2, 2048);
        CVT_STORE(v3, 3072);
#undef CVT_STORE
        return;
    }
    __shared__ float t[32][33];
    const int wb = bid - PA_BLKS - CL_BLKS - ED_BLKS;
    const int wz = wb >> 10;
    const int rem = wb & 1023;
    const int kb = (rem & 31) * 32, nb = (rem >> 5) * 32;
    const float* W = (wz == 0) ? Wq : (wz == 1) ? Wk : Wv;
    size_t ooff = (size_t)wz * D * D;
    int tx = threadIdx.x & 31, ty = threadIdx.x >> 5;
#pragma unroll
    for (int j = 0; j < 4; j++)
        t[ty + j * 8][tx] = W[(size_t)(kb + ty + j * 8) * D + nb + tx];
    __syncthreads();
#pragma unroll
    for (int j = 0; j < 4; j++) {
        int n = nb + ty + j * 8, kk = kb + tx;
        wt[ooff + (size_t)n * D + kk] = __float2half_rn(t[tx][ty + j * 8]);
    }
}

// =====================================================================
// Projection GEMM: pure fp16 single-pass, 3-stage cp.async ring,
// warp grid 4(m) x 2(n), K chunks of 64.  (frozen)
// =====================================================================
#define PST 144
#define ARR_B (128 * PST)
#define STAGE_B (2 * ARR_B)
#define PROJ_SMEM_BYTES (3 * STAGE_B)

__global__ void __launch_bounds__(256, 2) proj_mma(
    const __half* __restrict__ pa, const __half* __restrict__ cl,
    const __half* __restrict__ wt,
    const float* __restrict__ bq, const float* __restrict__ bk,
    const float* __restrict__ bv,
    __half* __restrict__ q, __half* __restrict__ k, __half* __restrict__ v)
{
    extern __shared__ char smem[];
    const uint32_t sbase = smem_u32(smem);
    const int tid = threadIdx.x;
    const int wid = tid >> 5, lane = tid & 31;

    const int bid = blockIdx.x;
    const __half *X, *W;
    const float* bias;
    __half* o;
    int mblk, Lsh; float scale;
    if (bid < 512) {
        X = pa; W = wt;
        bias = bq; o = q; Lsh = 11;
        scale = 0.125f * 1.44269504f;
        mblk = bid >> 3;
    } else if (bid < 640) {
        X = cl; W = wt + (size_t)D * D;
        bias = bk; o = k; Lsh = 9; scale = 1.0f;
        mblk = (bid - 512) >> 3;
    } else {
        X = cl; W = wt + (size_t)2 * D * D;
        bias = bv; o = v; Lsh = 9; scale = 1.0f;
        mblk = (bid - 640) >> 3;
    }
    const int n0 = (bid & 7) * 128;
    const int m0 = mblk * 128;

    const int wm = wid >> 1, wn = wid & 1;

    auto stage_load = [&](int stg, int k0) {
        const uint32_t sb = sbase + (uint32_t)stg * STAGE_B;
        const __half* srcs[2] = {X, W};
        const int rowoff[2] = {m0, n0};
#pragma unroll
        for (int a = 0; a < 2; a++) {
            const __half* s = srcs[a];
            uint32_t ab = sb + a * ARR_B;
#pragma unroll
            for (int i = 0; i < 4; i++) {
                int idx = tid + i * 256;
                int row = idx >> 3, seg = idx & 7;
                cp16(ab + row * PST + seg * 16,
                     s + (size_t)(rowoff[a] + row) * D + k0 + seg * 8);
            }
        }
    };

    float acc[2][8][4];
#pragma unroll
    for (int i = 0; i < 2; i++)
#pragma unroll
        for (int j = 0; j < 8; j++)
#pragma unroll
            for (int qq = 0; qq < 4; qq++) acc[i][j][qq] = 0.f;

    const int a_row_in = (lane & 7) + 8 * ((lane >> 3) & 1);
    const int a_colb = (lane >> 4) * 16;
    const int b4_row = ((lane >> 4) & 1) * 8 + (lane & 7);
    const int b4_colb = ((lane >> 3) & 1) * 16;

    stage_load(0, 0);
    CP_COMMIT();
    stage_load(1, 64);
    CP_COMMIT();
    CP_WAIT1();
    __syncthreads();

    for (int ck = 0; ck < 16; ck++) {
        if (ck + 2 < 16) stage_load((ck + 2) % 3, (ck + 2) * 64);
        CP_COMMIT();

        const uint32_t sb = sbase + (uint32_t)(ck % 3) * STAGE_B;
        const uint32_t xs = sb, ws = sb + ARR_B;

#pragma unroll
        for (int ks = 0; ks < 4; ks++) {
            const int kb = ks * 32;
            uint32_t bf[8][2];
#pragma unroll
            for (int pi = 0; pi < 4; pi++) {
                uint32_t boff =
                    (uint32_t)(wn * 64 + pi * 16 + b4_row) * PST + kb + b4_colb;
                ldsm_x4(bf[2 * pi][0], bf[2 * pi][1],
                        bf[2 * pi + 1][0], bf[2 * pi + 1][1], ws + boff);
            }
#pragma unroll
            for (int mi = 0; mi < 2; mi++) {
                uint32_t aoff =
                    (uint32_t)(wm * 32 + mi * 16 + a_row_in) * PST + kb + a_colb;
                uint32_t af[4];
                ldsm_x4(af[0], af[1], af[2], af[3], xs + aoff);
#pragma unroll
                for (int ni = 0; ni < 8; ni++) mma16816(acc[mi][ni], af, bf[ni]);
            }
        }
        CP_WAIT1();
        __syncthreads();
    }

    const int qr = lane >> 2;
    const int qc = (lane & 3) * 2;
    const int L = 1 << Lsh, Lm = L - 1;
#pragma unroll
    for (int mi = 0; mi < 2; mi++) {
#pragma unroll
        for (int rh = 0; rh < 2; rh++) {
            int m = m0 + wm * 32 + mi * 16 + qr + rh * 8;
            int bb = m >> Lsh, l = m & Lm;
#pragma unroll
            for (int ni = 0; ni < 8; ni++) {
                int n = n0 + wn * 64 + ni * 8 + qc;
                int hh = n >> 6, d0 = n & 63;
                float ox = (acc[mi][ni][rh * 2 + 0] + bias[n]) * scale;
                float oy = (acc[mi][ni][rh * 2 + 1] + bias[n + 1]) * scale;
                size_t off = (((size_t)bb * H + hh) * (size_t)L + l) * DH + d0;
                *(uint32_t*)(o + off) = pkhf(ox, oy);
            }
        }
    }
}

// =====================================================================
// Fused attention: pure fp16, fp16 edge, CT=64, double-buffered
// cp.async pipeline, exp2 softmax; fp16 ctx output.
// =====================================================================
#define AST 144
#define STG0 18432
#define STG_SZ 36864
#define ATTN_SMEM_BYTES (STG0 + 2 * STG_SZ)

__global__ void __launch_bounds__(256, 2) attn_mma(
    const __half* __restrict__ q, const __half* __restrict__ k,
    const __half* __restrict__ v,
    const __half* __restrict__ ed, __half* __restrict__ ctx)
{
    extern __shared__ char smem[];
    const uint32_t sbase = smem_u32(smem);
    const int tid = threadIdx.x;
    const int wid = tid >> 5, lane = tid & 31;
    const int b = blockIdx.z, h = blockIdx.y;
    const int p0 = blockIdx.x * 128;

    const size_t qoff = (((size_t)b * H + h) * P + p0) * DH;
    const size_t koff = (((size_t)b * H + h) * C) * DH;
    const __half* ebase = ed + ((size_t)b * P + p0) * C;

    auto load_chunk = [&](uint32_t stg, int cn) {
#pragma unroll
        for (int i = 0; i < 2; i++) {
            int idx = tid + i * 256;
            int row = idx >> 3, seg = idx & 7;
            cp16(stg + row * AST + seg * 16,
                 k + koff + (size_t)(cn + row) * DH + seg * 8);
            cp16(stg + 9216 + row * AST + seg * 16,
                 v + koff + (size_t)(cn + row) * DH + seg * 8);
        }
#pragma unroll
        for (int i = 0; i < 4; i++) {
            int idx = tid + i * 256;
            int er = idx >> 3, seg = idx & 7;
            cp16(stg + 18432 + er * AST + seg * 16,
                 ebase + (size_t)er * C + cn + seg * 8);
        }
    };

#pragma unroll
    for (int i = 0; i < 4; i++) {
        int g = tid + i * 256;
        int row = g >> 3, seg = g & 7;
        cp16(sbase + row * AST + seg * 16,
             q + qoff + (size_t)row * DH + seg * 8);
    }
    load_chunk(sbase + STG0, 0);
    CP_COMMIT();

    const int a_row = (lane & 7) + 8 * ((lane >> 3) & 1);
    const int a_colb = (lane >> 4) * 16;
    const int b4_row = ((lane >> 4) & 1) * 8 + (lane & 7);
    const int b4_colb = ((lane >> 3) & 1) * 16;
    const int r0 = lane >> 2;
    const int wr = wid * 16;
    const int c2 = (lane & 3) * 2;

    CP_WAIT0();
    __syncthreads();

    uint32_t qf[4][4];
#pragma unroll
    for (int ks = 0; ks < 4; ks++) {
        uint32_t aoff = (uint32_t)(wr + a_row) * AST + a_colb + ks * 32;
        ldsm_x4(qf[ks][0], qf[ks][1], qf[ks][2], qf[ks][3], sbase + aoff);
    }

    float m_r[2] = {-1e30f, -1e30f};
    float l_r[2] = {0.f, 0.f};
    float cacc[8][4];
#pragma unroll
    for (int i = 0; i < 8; i++)
#pragma unroll
        for (int j = 0; j < 4; j++) cacc[i][j] = 0.f;

    for (int ck = 0; ck < 8; ck++) {
        const uint32_t stgoff = STG0 + (uint32_t)(ck & 1) * STG_SZ;
        const uint32_t stg = sbase + stgoff;

        if (ck < 7) {
            load_chunk(sbase + STG0 + (uint32_t)((ck + 1) & 1) * STG_SZ,
                       (ck + 1) * 64);
            CP_COMMIT();
        }

        float s[8][4];
#pragma unroll
        for (int i = 0; i < 8; i++)
#pragma unroll
            for (int j = 0; j < 4; j++) s[i][j] = 0.f;

#pragma unroll
        for (int ks = 0; ks < 4; ks++) {
            uint32_t bf[8][2];
#pragma unroll
            for (int pi = 0; pi < 4; pi++) {
                uint32_t boff =
                    (uint32_t)(pi * 16 + b4_row) * AST + b4_colb + ks * 32;
                ldsm_x4(bf[2 * pi][0], bf[2 * pi][1],
                        bf[2 * pi + 1][0], bf[2 * pi + 1][1], stg + boff);
            }
#pragma unroll
            for (int ni = 0; ni < 8; ni++) mma16816(s[ni], qf[ks], bf[ni]);
        }

        float alpha[2];
#pragma unroll
        for (int rr = 0; rr < 2; rr++) {
            const __half* ep = (const __half*)(smem + stgoff + 18432 +
                                (size_t)(wr + r0 + rr * 8) * AST) + c2;
            float ev[8][2];
            float mx = -1e30f;
#pragma unroll
            for (int j = 0; j < 8; j++) {
                float2 e2 = __half22float2(*(const __half2*)(ep + j * 8));
                ev[j][0] = e2.x; ev[j][1] = e2.y;
                float s0 = (e2.x > 0.f) ? s[j][rr * 2] : -1e30f;
                float s1 = (e2.y > 0.f) ? s[j][rr * 2 + 1] : -1e30f;
                s[j][rr * 2] = s0; s[j][rr * 2 + 1] = s1;
                mx = fmaxf(mx, fmaxf(s0, s1));
            }
            mx = fmaxf(mx, __shfl_xor_sync(0xffffffffu, mx, 1));
            mx = fmaxf(mx, __shfl_xor_sync(0xffffffffu, mx, 2));
            float mn = fmaxf(m_r[rr], mx);
            alpha[rr] = exp2r(m_r[rr] - mn);
            m_r[rr] = mn;
            float ls = 0.f;
#pragma unroll
            for (int j = 0; j < 8; j++) {
                float ex0 = exp2r(s[j][rr * 2] - mn);
                float ex1 = exp2r(s[j][rr * 2 + 1] - mn);
                ls += ex0 + ex1;
                s[j][rr * 2] = ex0 * ev[j][0];
                s[j][rr * 2 + 1] = ex1 * ev[j][1];
            }
            ls += __shfl_xor_sync(0xffffffffu, ls, 1);
            ls += __shfl_xor_sync(0xffffffffu, ls, 2);
            l_r[rr] = l_r[rr] * alpha[rr] + ls;
        }

#pragma unroll
        for (int ni = 0; ni < 8; ni++) {
            cacc[ni][0] *= alpha[0]; cacc[ni][1] *= alpha[0];
            cacc[ni][2] *= alpha[1]; cacc[ni][3] *= alpha[1];
        }
#pragma unroll
        for (int ks = 0; ks < 4; ks++) {
            const float* t0 = s[2 * ks];
            const float* t1 = s[2 * ks + 1];
            uint32_t ap[4];
            ap[0] = pkhf(t0[0], t0[1]);
            ap[1] = pkhf(t0[2], t0[3]);
            ap[2] = pkhf(t1[0], t1[1]);
            ap[3] = pkhf(t1[2], t1[3]);
            uint32_t vrow = (uint32_t)(ks * 16 + (lane & 15)) * AST;
            uint32_t vf[8][2];
#pragma unroll
            for (int ni = 0; ni < 8; ni++)
                ldsm_x2t(vf[ni][0], vf[ni][1], stg + 9216 + vrow + ni * 16);
#pragma unroll
            for (int ni = 0; ni < 8; ni++) mma16816(cacc[ni], ap, vf[ni]);
        }

        if (ck < 7) {
            CP_WAIT0();
            __syncthreads();
        }
    }

    // fp16 ctx output
    const float inv0 = 1.0f / l_r[0];
    const float inv1 = 1.0f / l_r[1];
    const int row0 = p0 + wr + r0;
#pragma unroll
    for (int ni = 0; ni < 8; ni++) {
        int dh = ni * 8 + c2;
        size_t base0 = ((size_t)b * P + row0) * D + h * DH + dh;
        *(uint32_t*)(ctx + base0) =
            pkhf(cacc[ni][0] * inv0, cacc[ni][1] * inv0);
        *(uint32_t*)(ctx + base0 + (size_t)8 * D) =
            pkhf(cacc[ni][2] * inv1, cacc[ni][3] * inv1);
    }
}

// =====================================================================
// LayerNorm over D=1024 from fp16 ctx: 4 rows per block, MLP=4.
// =====================================================================
__global__ void __launch_bounds__(256) ln_kernel(
    const __half* __restrict__ x, const float* __restrict__ gamma,
    const float* __restrict__ beta, float* __restrict__ out)
{
    __shared__ float rs1[4][8], rs2[4][8];
    const size_t row0 = (size_t)blockIdx.x * 4;
    const int tid = threadIdx.x;

    // each thread: 4 contiguous elems per row (8B = half4), 4 rows
    uint2 raw[4];
#pragma unroll
    for (int r = 0; r < 4; r++)
        raw[r] = *(const uint2*)(x + (row0 + r) * D + tid * 4);

    float xv[4][4];
    float s1[4], s2[4];
#pragma unroll
    for (int r = 0; r < 4; r++) {
        float2 a = __half22float2(*(__half2*)&raw[r].x);
        float2 bb = __half22float2(*(__half2*)&raw[r].y);
        xv[r][0] = a.x; xv[r][1] = a.y; xv[r][2] = bb.x; xv[r][3] = bb.y;
        s1[r] = (a.x + a.y) + (bb.x + bb.y);
        s2[r] = (a.x * a.x + a.y * a.y) + (bb.x * bb.x + bb.y * bb.y);
    }
#pragma unroll
    for (int o = 16; o; o >>= 1) {
#pragma unroll
        for (int r = 0; r < 4; r++) {
            s1[r] += __shfl_xor_sync(0xffffffffu, s1[r], o);
            s2[r] += __shfl_xor_sync(0xffffffffu, s2[r], o);
        }
    }
    if ((tid & 31) == 0) {
#pragma unroll
        for (int r = 0; r < 4; r++) {
            rs1[r][tid >> 5] = s1[r];
            rs2[r][tid >> 5] = s2[r];
        }
    }
    __syncthreads();
    if (tid < 32) {
        float t1[4], t2[4];
#pragma unroll
        for (int r = 0; r < 4; r++) {
            t1[r] = (tid < 8) ? rs1[r][tid] : 0.f;
            t2[r] = (tid < 8) ? rs2[r][tid] : 0.f;
        }
#pragma unroll
        for (int o = 4; o; o >>= 1) {
#pragma unroll
            for (int r = 0; r < 4; r++) {
                t1[r] += __shfl_xor_sync(0xffffffffu, t1[r], o);
                t2[r] += __shfl_xor_sync(0xffffffffu, t2[r], o);
            }
        }
        if (tid == 0) {
#pragma unroll
            for (int r = 0; r < 4; r++) {
                rs1[r][0] = t1[r];
                rs2[r][0] = t2[r];
            }
        }
    }
    __syncthreads();
    const float4 g = *(const float4*)(gamma + tid * 4);
    const float4 bt = *(const float4*)(beta + tid * 4);
#pragma unroll
    for (int r = 0; r < 4; r++) {
        const float mu = rs1[r][0] * (1.0f / D);
        const float var = fmaxf(rs2[r][0] * (1.0f / D) - mu * mu, 0.f);
        const float rr = rsqrtf(var + 1e-6f);
        float4 o;
        o.x = (xv[r][0] - mu) * rr * g.x + bt.x;
        o.y = (xv[r][1] - mu) * rr * g.y + bt.y;
        o.z = (xv[r][2] - mu) * rr * g.z + bt.z;
        o.w = (xv[r][3] - mu) * rr * g.w + bt.w;
        *(float4*)(out + (row0 + r) * D + tid * 4) = o;
    }
}

// =====================================================================
extern "C" void kernel_launch(void* const* d_in, const int* in_sizes, int n_in,
                              void* d_out, int out_size)
{
    const float* para    = (const float*)d_in[0];
    const float* cluster = (const float*)d_in[1];
    const float* edge    = (const float*)d_in[2];
    const float* Wq = (const float*)d_in[3];
    const float* bq = (const float*)d_in[4];
    const float* Wk = (const float*)d_in[5];
    const float* bk = (const float*)d_in[6];
    const float* Wv = (const float*)d_in[7];
    const float* bv = (const float*)d_in[8];
    const float* gamma = (const float*)d_in[9];
    const float* beta  = (const float*)d_in[10];
    float* out = (float*)d_out;

    __half *cp, *qp, *kp, *vp, *pap, *clp, *wtp, *edp;
    cudaGetSymbolAddress((void**)&cp, g_ctx);
    cudaGetSymbolAddress((void**)&qp, g_q);
    cudaGetSymbolAddress((void**)&kp, g_k);
    cudaGetSymbolAddress((void**)&vp, g_v);
    cudaGetSymbolAddress((void**)&pap, g_pa);
    cudaGetSymbolAddress((void**)&clp, g_cl);
    cudaGetSymbolAddress((void**)&wtp, g_wt);
    cudaGetSymbolAddress((void**)&edp, g_ed);

    cudaFuncSetAttribute(proj_mma,
                         cudaFuncAttributeMaxDynamicSharedMemorySize,
                         PROJ_SMEM_BYTES);
    cudaFuncSetAttribute(attn_mma,
                         cudaFuncAttributeMaxDynamicSharedMemorySize,
                         ATTN_SMEM_BYTES);

    prep_all<<<PREP_BLKS, 256>>>(para, cluster, edge, Wq, Wk, Wv,
                                 pap, clp, edp, wtp);

    proj_mma<<<768, 256, PROJ_SMEM_BYTES>>>(pap, clp, wtp, bq, bk, bv,
                                            qp, kp, vp);

    attn_mma<<<dim3(P / 128, H, B), 256, ATTN_SMEM_BYTES>>>(
        qp, kp, vp, edp, cp);

    ln_kernel<<<(B * P) / 4, 256>>>(cp, gamma, beta, out);
}